// round 3
// baseline (speedup 1.0000x reference)
#include <cuda_runtime.h>
#include <math.h>

// Problem constants (fixed by the dataset instance)
#define M_TOK 16384   // B*S = 4*4096
#define DDIM  1024    // model dim = H*Khead = 16*64
// windows: 8 of 512 tokens; heads: 16 of dim 64

// Static device scratch (allocation-free rule): 3 x 64MB
// g_Q: Q, then (in-place) attention context, then dead
// g_K: K, then Y (= ctx@Wo + bo + x)
// g_V: V
__device__ float g_Q[(size_t)M_TOK * DDIM];
__device__ float g_K[(size_t)M_TOK * DDIM];
__device__ float g_V[(size_t)M_TOK * DDIM];

// ---------------------------------------------------------------------------
// SGEMM: C[M,1024] = A[M,1024] @ Bm[1024,1024] + bias[col] (+ resid[row,col])
// 128x128 block tile, BK=16, 256 threads, 8x8 per-thread microtile.
// ---------------------------------------------------------------------------
__global__ __launch_bounds__(256) void sgemm_kernel(
    const float* __restrict__ A, const float* __restrict__ Bm,
    const float* __restrict__ bias, const float* __restrict__ resid,
    float* __restrict__ C)
{
    __shared__ float As[16][128];   // transposed A tile: As[k][m]
    __shared__ float Bs[16][128];   // Bs[k][n]

    int tid = threadIdx.x;
    int tx = tid & 15, ty = tid >> 4;
    int row0 = blockIdx.y << 7;
    int col0 = blockIdx.x << 7;

    float acc[8][8];
#pragma unroll
    for (int i = 0; i < 8; i++)
#pragma unroll
        for (int j = 0; j < 8; j++) acc[i][j] = 0.f;

    int ar = tid >> 2, ac = (tid & 3) << 2;   // A: 128 rows x 16 cols
    int br = tid >> 5, bc = (tid & 31) << 2;  // B: 16 rows x 128 cols

    for (int k0 = 0; k0 < DDIM; k0 += 16) {
#pragma unroll
        for (int p = 0; p < 2; p++) {
            float4 v = *(const float4*)(A + (size_t)(row0 + ar + 64 * p) * DDIM + k0 + ac);
            As[ac + 0][ar + 64 * p] = v.x;
            As[ac + 1][ar + 64 * p] = v.y;
            As[ac + 2][ar + 64 * p] = v.z;
            As[ac + 3][ar + 64 * p] = v.w;
        }
#pragma unroll
        for (int p = 0; p < 2; p++) {
            *(float4*)&Bs[br + 8 * p][bc] =
                *(const float4*)(Bm + (size_t)(k0 + br + 8 * p) * DDIM + col0 + bc);
        }
        __syncthreads();

#pragma unroll
        for (int kk = 0; kk < 16; kk++) {
            float a[8], b[8];
            *(float4*)&a[0] = *(float4*)&As[kk][(ty << 3)];
            *(float4*)&a[4] = *(float4*)&As[kk][(ty << 3) + 4];
            *(float4*)&b[0] = *(float4*)&Bs[kk][(tx << 3)];
            *(float4*)&b[4] = *(float4*)&Bs[kk][(tx << 3) + 4];
#pragma unroll
            for (int i = 0; i < 8; i++)
#pragma unroll
                for (int j = 0; j < 8; j++)
                    acc[i][j] = fmaf(a[i], b[j], acc[i][j]);
        }
        __syncthreads();
    }

#pragma unroll
    for (int i = 0; i < 8; i++) {
        size_t row = (size_t)row0 + (ty << 3) + i;
        int col = col0 + (tx << 3);
#pragma unroll
        for (int j4 = 0; j4 < 8; j4 += 4) {
            float4 o;
            o.x = acc[i][j4 + 0] + bias[col + j4 + 0];
            o.y = acc[i][j4 + 1] + bias[col + j4 + 1];
            o.z = acc[i][j4 + 2] + bias[col + j4 + 2];
            o.w = acc[i][j4 + 3] + bias[col + j4 + 3];
            if (resid) {
                float4 rv = *(const float4*)(resid + row * DDIM + col + j4);
                o.x += rv.x; o.y += rv.y; o.z += rv.z; o.w += rv.w;
            }
            *(float4*)(C + row * DDIM + col + j4) = o;
        }
    }
}

// ---------------------------------------------------------------------------
// Windowed attention. Block = (32 q-rows, one (b,w,h) head). 256 threads.
// Full 32x512 score tile in smem, block softmax, then PV accumulate.
// Output written IN-PLACE over the Q buffer (safe: each block consumes its
// own Q tile into smem before writing, and blocks' output regions are
// exactly their own Q regions — disjoint across blocks).
// dyn smem: Ssm 32*512 + Qs 32*65 + KVs 64*65 = 22624 floats = 90496 B
// ---------------------------------------------------------------------------
__global__ __launch_bounds__(256) void attn_kernel(
    const float* __restrict__ Km, const float* __restrict__ V,
    float* __restrict__ QC)   // Q in, context out (in-place)
{
    extern __shared__ float sm[];
    float* Ssm = sm;                 // [32][512]
    float* Qs  = sm + 32 * 512;      // [32][65] padded
    float* KVs = Qs + 32 * 65;       // [64][65] padded

    int tid = threadIdx.x;
    int hid = blockIdx.y;            // 0..511 = (b, w, h)
    int b = hid >> 7;
    int w = (hid >> 4) & 7;
    int h = hid & 15;
    int t0 = b * 4096 + w * 512;     // window token base
    int hcol = h << 6;               // head column offset
    int qbase = blockIdx.x << 5;     // q-tile base within window

    // load Q tile [32][64]
    {
        int r = tid >> 4, c4 = (tid & 15) << 2;
#pragma unroll
        for (int p = 0; p < 2; p++) {
            float4 v = *(const float4*)(QC + (size_t)(t0 + qbase + r + 16 * p) * DDIM + hcol + c4);
            float* dst = &Qs[(r + 16 * p) * 65 + c4];
            dst[0] = v.x; dst[1] = v.y; dst[2] = v.z; dst[3] = v.w;
        }
    }

    int j0 = (tid & 15) << 2;        // 4 score cols / output dims per thread
    int r0 = (tid >> 4) << 1;        // 2 q-rows per thread

    // ---- scores: S[32][512] = Q Kt^T, tile by 64 keys ----
    for (int kt = 0; kt < 8; kt++) {
        __syncthreads();
        {
            int r = tid >> 4, c4 = (tid & 15) << 2;
#pragma unroll
            for (int p = 0; p < 4; p++) {
                float4 v = *(const float4*)(Km + (size_t)(t0 + kt * 64 + r + 16 * p) * DDIM + hcol + c4);
                float* dst = &KVs[(r + 16 * p) * 65 + c4];
                dst[0] = v.x; dst[1] = v.y; dst[2] = v.z; dst[3] = v.w;
            }
        }
        __syncthreads();

        float acc[2][4] = {{0, 0, 0, 0}, {0, 0, 0, 0}};
#pragma unroll 8
        for (int d = 0; d < 64; d++) {
            float q0 = Qs[r0 * 65 + d];
            float q1 = Qs[(r0 + 1) * 65 + d];
#pragma unroll
            for (int u = 0; u < 4; u++) {
                float kv = KVs[(j0 + u) * 65 + d];
                acc[0][u] = fmaf(q0, kv, acc[0][u]);
                acc[1][u] = fmaf(q1, kv, acc[1][u]);
            }
        }
#pragma unroll
        for (int i = 0; i < 2; i++)
#pragma unroll
            for (int u = 0; u < 4; u++)
                Ssm[(r0 + i) * 512 + kt * 64 + j0 + u] = acc[i][u];
    }
    __syncthreads();

    // ---- softmax over 512 keys, scale 1/sqrt(64) = 0.125 ----
    {
        int lane = tid & 31, wid = tid >> 5;
#pragma unroll
        for (int q = 0; q < 4; q++) {
            int r = wid * 4 + q;
            float vals[16];
            float m = -1e30f;
#pragma unroll
            for (int t = 0; t < 16; t++) {
                vals[t] = Ssm[r * 512 + lane + 32 * t];
                m = fmaxf(m, vals[t]);
            }
#pragma unroll
            for (int off = 16; off > 0; off >>= 1)
                m = fmaxf(m, __shfl_xor_sync(0xffffffffu, m, off));
            float s = 0.f;
#pragma unroll
            for (int t = 0; t < 16; t++) {
                float e = __expf((vals[t] - m) * 0.125f);
                vals[t] = e;
                s += e;
            }
#pragma unroll
            for (int off = 16; off > 0; off >>= 1)
                s += __shfl_xor_sync(0xffffffffu, s, off);
            float inv = 1.0f / s;
#pragma unroll
            for (int t = 0; t < 16; t++)
                Ssm[r * 512 + lane + 32 * t] = vals[t] * inv;
        }
    }

    // ---- O[32][64] = P[32][512] @ V[512][64] ----
    float oacc[2][4] = {{0, 0, 0, 0}, {0, 0, 0, 0}};
    for (int kt = 0; kt < 8; kt++) {
        __syncthreads();   // also orders softmax writes before first read
        {
            int r = tid >> 4, c4 = (tid & 15) << 2;
#pragma unroll
            for (int p = 0; p < 4; p++) {
                float4 v = *(const float4*)(V + (size_t)(t0 + kt * 64 + r + 16 * p) * DDIM + hcol + c4);
                float* dst = &KVs[(r + 16 * p) * 65 + c4];
                dst[0] = v.x; dst[1] = v.y; dst[2] = v.z; dst[3] = v.w;
            }
        }
        __syncthreads();
#pragma unroll 8
        for (int j = 0; j < 64; j++) {
            float p0 = Ssm[r0 * 512 + kt * 64 + j];
            float p1 = Ssm[(r0 + 1) * 512 + kt * 64 + j];
#pragma unroll
            for (int u = 0; u < 4; u++) {
                float vv = KVs[j * 65 + j0 + u];
                oacc[0][u] = fmaf(p0, vv, oacc[0][u]);
                oacc[1][u] = fmaf(p1, vv, oacc[1][u]);
            }
        }
    }
#pragma unroll
    for (int i = 0; i < 2; i++) {
        size_t row = (size_t)(t0 + qbase + r0 + i);
#pragma unroll
        for (int u = 0; u < 4; u++)
            QC[row * DDIM + hcol + j0 + u] = oacc[i][u];
    }
}

// ---------------------------------------------------------------------------
// LayerNorm per row (1024 elems), keras eps = 1e-3. One block per row.
// ---------------------------------------------------------------------------
__global__ __launch_bounds__(256) void ln_kernel(
    const float* __restrict__ Y, const float* __restrict__ gamma,
    const float* __restrict__ beta, float* __restrict__ out)
{
    int row = blockIdx.x;
    int tid = threadIdx.x;
    const float* y = Y + (size_t)row * DDIM;

    float4 v = *(const float4*)(y + tid * 4);
    float s  = v.x + v.y + v.z + v.w;
    float sq = v.x * v.x + v.y * v.y + v.z * v.z + v.w * v.w;

#pragma unroll
    for (int off = 16; off > 0; off >>= 1) {
        s  += __shfl_xor_sync(0xffffffffu, s, off);
        sq += __shfl_xor_sync(0xffffffffu, sq, off);
    }
    __shared__ float ss[8], ssq[8];
    int lane = tid & 31, wid = tid >> 5;
    if (lane == 0) { ss[wid] = s; ssq[wid] = sq; }
    __syncthreads();
    float S = 0.f, SQ = 0.f;
#pragma unroll
    for (int i = 0; i < 8; i++) { S += ss[i]; SQ += ssq[i]; }

    float mu  = S * (1.0f / 1024.0f);
    float var = SQ * (1.0f / 1024.0f) - mu * mu;
    float inv = rsqrtf(var + 1e-3f);

    float4 g  = *(const float4*)(gamma + tid * 4);
    float4 be = *(const float4*)(beta + tid * 4);
    float4 o;
    o.x = (v.x - mu) * inv * g.x + be.x;
    o.y = (v.y - mu) * inv * g.y + be.y;
    o.z = (v.z - mu) * inv * g.z + be.z;
    o.w = (v.w - mu) * inv * g.w + be.w;
    *(float4*)(out + (size_t)row * DDIM + tid * 4) = o;
}

// ---------------------------------------------------------------------------
extern "C" void kernel_launch(void* const* d_in, const int* in_sizes, int n_in,
                              void* d_out, int out_size)
{
    const float* x     = (const float*)d_in[0];
    const float* Wq    = (const float*)d_in[1];
    const float* bq    = (const float*)d_in[2];
    const float* Wk    = (const float*)d_in[3];
    const float* bk    = (const float*)d_in[4];
    const float* Wv    = (const float*)d_in[5];
    const float* bv    = (const float*)d_in[6];
    const float* Wo    = (const float*)d_in[7];
    const float* bo    = (const float*)d_in[8];
    const float* gamma = (const float*)d_in[9];
    const float* beta  = (const float*)d_in[10];
    float* out = (float*)d_out;
    (void)in_sizes; (void)n_in; (void)out_size;

    float *Qp, *Kp, *Vp;
    cudaGetSymbolAddress((void**)&Qp, g_Q);
    cudaGetSymbolAddress((void**)&Kp, g_K);
    cudaGetSymbolAddress((void**)&Vp, g_V);

    const int ATTN_SMEM = 90496;
    cudaFuncSetAttribute(attn_kernel, cudaFuncAttributeMaxDynamicSharedMemorySize, ATTN_SMEM);

    dim3 gg(8, 128);  // (N/128, M/128)
    sgemm_kernel<<<gg, 256>>>(x, Wq, bq, nullptr, Qp);
    sgemm_kernel<<<gg, 256>>>(x, Wk, bk, nullptr, Kp);
    sgemm_kernel<<<gg, 256>>>(x, Wv, bv, nullptr, Vp);

    // ctx overwrites Q in-place
    attn_kernel<<<dim3(16, 512), 256, ATTN_SMEM>>>(Kp, Vp, Qp);

    // Y = ctx @ Wo + bo + x   (write Y into g_K, dead after attention)
    sgemm_kernel<<<gg, 256>>>(Qp, Wo, bo, x, Kp);

    ln_kernel<<<M_TOK, 256>>>(Kp, gamma, beta, out);
}

// round 4
// speedup vs baseline: 1.5041x; 1.5041x over previous
#include <cuda_runtime.h>
#include <math.h>
#include <stdint.h>

// Problem constants (fixed by the dataset instance)
#define M_TOK 16384   // B*S = 4*4096
#define DDIM  1024    // model dim = H*Khead = 16*64
// windows: 8 of 512 tokens; heads: 16 of dim 64

// Static device scratch (allocation-free rule): 3 x 64MB
// g_Q: Q, then (in-place) attention context, then dead
// g_K: K, then Y (= ctx@Wo + bo + x)
// g_V: V
__device__ float g_Q[(size_t)M_TOK * DDIM];
__device__ float g_K[(size_t)M_TOK * DDIM];
__device__ float g_V[(size_t)M_TOK * DDIM];

__device__ __forceinline__ float f2tf32(float x) {
    uint32_t u;
    asm("cvt.rna.tf32.f32 %0, %1;" : "=r"(u) : "f"(x));
    return __uint_as_float(u);
}

__device__ __forceinline__ void mma_tf32(
    float& d0, float& d1, float& d2, float& d3,
    uint32_t a0, uint32_t a1, uint32_t a2, uint32_t a3,
    uint32_t b0, uint32_t b1)
{
    asm volatile(
        "mma.sync.aligned.m16n8k8.row.col.f32.tf32.tf32.f32 "
        "{%0,%1,%2,%3}, {%4,%5,%6,%7}, {%8,%9}, {%0,%1,%2,%3};"
        : "+f"(d0), "+f"(d1), "+f"(d2), "+f"(d3)
        : "r"(a0), "r"(a1), "r"(a2), "r"(a3), "r"(b0), "r"(b1));
}

// ---------------------------------------------------------------------------
// TF32 tensor-core GEMM: C[M,1024] = A[M,1024] @ Bm[1024,1024] + bias[col]
// (+ resid). 128x128x32 block tile, 256 threads = 8 warps (4 m x 2 n),
// warp tile 32x64 via m16n8k8 tf32 mma. fp32 accumulate.
// Smem padded for conflict-free fragment loads:
//   As[128][36]: frag addr bank = gid*4 + tig  (unique over warp)
//   Bs[32][136]: frag addr bank = tig*8 + gid  (unique over warp)
// ---------------------------------------------------------------------------
__global__ __launch_bounds__(256) void tf32_gemm_kernel(
    const float* __restrict__ A, const float* __restrict__ Bm,
    const float* __restrict__ bias, const float* __restrict__ resid,
    float* __restrict__ C)
{
    __shared__ float As[128][36];
    __shared__ float Bs[32][136];

    int tid = threadIdx.x;
    int lane = tid & 31, wid = tid >> 5;
    int warp_m = wid & 3;          // 4 warps over M: 32 rows each
    int warp_n = wid >> 2;         // 2 warps over N: 64 cols each
    int gid = lane >> 2, tig = lane & 3;

    int row0 = blockIdx.y << 7;
    int col0 = blockIdx.x << 7;

    float acc[2][8][4];            // [mtile 16][ntile 8][c-regs]
#pragma unroll
    for (int mt = 0; mt < 2; mt++)
#pragma unroll
        for (int nt = 0; nt < 8; nt++)
#pragma unroll
            for (int r = 0; r < 4; r++) acc[mt][nt][r] = 0.f;

    // global->smem staging indices
    int rowA = tid >> 1;               // 0..127
    int colA0 = (tid & 1) << 4;        // 0 or 16 (floats)
    int rowB = tid >> 3;               // 0..31
    int colB0 = (tid & 7) << 4;        // 0..112 step 16

    const float* Ag = A + (size_t)(row0 + rowA) * DDIM + colA0;
    const float* Bg = Bm + (size_t)rowB * DDIM + col0 + colB0;

    for (int k0 = 0; k0 < DDIM; k0 += 32) {
        // fetch to regs first (hide behind previous compute drain)
        float4 av[4], bv[4];
#pragma unroll
        for (int p = 0; p < 4; p++) av[p] = *(const float4*)(Ag + k0 + p * 4);
#pragma unroll
        for (int p = 0; p < 4; p++) bv[p] = *(const float4*)(Bg + (size_t)k0 * DDIM + p * 4);

        __syncthreads();   // previous iter's compute done reading smem
#pragma unroll
        for (int p = 0; p < 4; p++) {
            float4 t;
            t.x = f2tf32(av[p].x); t.y = f2tf32(av[p].y);
            t.z = f2tf32(av[p].z); t.w = f2tf32(av[p].w);
            *(float4*)&As[rowA][colA0 + p * 4] = t;
            float4 u;
            u.x = f2tf32(bv[p].x); u.y = f2tf32(bv[p].y);
            u.z = f2tf32(bv[p].z); u.w = f2tf32(bv[p].w);
            *(float4*)&Bs[rowB][colB0 + p * 4] = u;
        }
        __syncthreads();

#pragma unroll
        for (int ks = 0; ks < 4; ks++) {
            int kk = ks << 3;
            uint32_t af[2][4];
            int mrow = (warp_m << 5) + gid;
#pragma unroll
            for (int mt = 0; mt < 2; mt++) {
                int r = mrow + (mt << 4);
                af[mt][0] = __float_as_uint(As[r][kk + tig]);
                af[mt][1] = __float_as_uint(As[r + 8][kk + tig]);
                af[mt][2] = __float_as_uint(As[r][kk + tig + 4]);
                af[mt][3] = __float_as_uint(As[r + 8][kk + tig + 4]);
            }
            uint32_t bf[8][2];
            int nbase = (warp_n << 6) + gid;
#pragma unroll
            for (int nt = 0; nt < 8; nt++) {
                int c = nbase + (nt << 3);
                bf[nt][0] = __float_as_uint(Bs[kk + tig][c]);
                bf[nt][1] = __float_as_uint(Bs[kk + tig + 4][c]);
            }
#pragma unroll
            for (int mt = 0; mt < 2; mt++)
#pragma unroll
                for (int nt = 0; nt < 8; nt++)
                    mma_tf32(acc[mt][nt][0], acc[mt][nt][1],
                             acc[mt][nt][2], acc[mt][nt][3],
                             af[mt][0], af[mt][1], af[mt][2], af[mt][3],
                             bf[nt][0], bf[nt][1]);
        }
    }

    // epilogue: bias (+resid), float2 stores
#pragma unroll
    for (int mt = 0; mt < 2; mt++) {
#pragma unroll
        for (int nt = 0; nt < 8; nt++) {
            int col = col0 + (warp_n << 6) + (nt << 3) + (tig << 1);
            float bx = bias[col], by = bias[col + 1];
#pragma unroll
            for (int h = 0; h < 2; h++) {   // h=0: rows gid, h=1: rows gid+8
                size_t row = (size_t)row0 + (warp_m << 5) + (mt << 4) + gid + (h << 3);
                float2 o;
                o.x = acc[mt][nt][2 * h + 0] + bx;
                o.y = acc[mt][nt][2 * h + 1] + by;
                if (resid) {
                    float2 rv = *(const float2*)(resid + row * DDIM + col);
                    o.x += rv.x; o.y += rv.y;
                }
                *(float2*)(C + row * DDIM + col) = o;
            }
        }
    }
}

// ---------------------------------------------------------------------------
// Windowed attention. Block = (32 q-rows, one (b,w,h) head). 256 threads.
// Full 32x512 score tile in smem, block softmax, then PV accumulate.
// Output written IN-PLACE over the Q buffer (each block consumes its own Q
// tile into smem before writing; block output regions are disjoint).
// dyn smem: Ssm 32*512 + Qs 32*65 + KVs 64*65 = 22624 floats = 90496 B
// ---------------------------------------------------------------------------
__global__ __launch_bounds__(256) void attn_kernel(
    const float* __restrict__ Km, const float* __restrict__ V,
    float* __restrict__ QC)   // Q in, context out (in-place)
{
    extern __shared__ float sm[];
    float* Ssm = sm;                 // [32][512]
    float* Qs  = sm + 32 * 512;      // [32][65] padded
    float* KVs = Qs + 32 * 65;       // [64][65] padded

    int tid = threadIdx.x;
    int hid = blockIdx.y;            // 0..511 = (b, w, h)
    int b = hid >> 7;
    int w = (hid >> 4) & 7;
    int h = hid & 15;
    int t0 = b * 4096 + w * 512;     // window token base
    int hcol = h << 6;               // head column offset
    int qbase = blockIdx.x << 5;     // q-tile base within window

    // load Q tile [32][64]
    {
        int r = tid >> 4, c4 = (tid & 15) << 2;
#pragma unroll
        for (int p = 0; p < 2; p++) {
            float4 v = *(const float4*)(QC + (size_t)(t0 + qbase + r + 16 * p) * DDIM + hcol + c4);
            float* dst = &Qs[(r + 16 * p) * 65 + c4];
            dst[0] = v.x; dst[1] = v.y; dst[2] = v.z; dst[3] = v.w;
        }
    }

    int j0 = (tid & 15) << 2;        // 4 score cols / output dims per thread
    int r0 = (tid >> 4) << 1;        // 2 q-rows per thread

    // ---- scores: S[32][512] = Q K^T, tile by 64 keys ----
    for (int kt = 0; kt < 8; kt++) {
        __syncthreads();
        {
            int r = tid >> 4, c4 = (tid & 15) << 2;
#pragma unroll
            for (int p = 0; p < 4; p++) {
                float4 v = *(const float4*)(Km + (size_t)(t0 + kt * 64 + r + 16 * p) * DDIM + hcol + c4);
                float* dst = &KVs[(r + 16 * p) * 65 + c4];
                dst[0] = v.x; dst[1] = v.y; dst[2] = v.z; dst[3] = v.w;
            }
        }
        __syncthreads();

        float acc[2][4] = {{0, 0, 0, 0}, {0, 0, 0, 0}};
#pragma unroll 8
        for (int d = 0; d < 64; d++) {
            float q0 = Qs[r0 * 65 + d];
            float q1 = Qs[(r0 + 1) * 65 + d];
#pragma unroll
            for (int u = 0; u < 4; u++) {
                float kv = KVs[(j0 + u) * 65 + d];
                acc[0][u] = fmaf(q0, kv, acc[0][u]);
                acc[1][u] = fmaf(q1, kv, acc[1][u]);
            }
        }
#pragma unroll
        for (int i = 0; i < 2; i++)
#pragma unroll
            for (int u = 0; u < 4; u++)
                Ssm[(r0 + i) * 512 + kt * 64 + j0 + u] = acc[i][u];
    }
    __syncthreads();

    // ---- softmax over 512 keys, scale 1/sqrt(64) = 0.125 ----
    {
        int lane = tid & 31, wd = tid >> 5;
#pragma unroll
        for (int q = 0; q < 4; q++) {
            int r = wd * 4 + q;
            float vals[16];
            float m = -1e30f;
#pragma unroll
            for (int t = 0; t < 16; t++) {
                vals[t] = Ssm[r * 512 + lane + 32 * t];
                m = fmaxf(m, vals[t]);
            }
#pragma unroll
            for (int off = 16; off > 0; off >>= 1)
                m = fmaxf(m, __shfl_xor_sync(0xffffffffu, m, off));
            float s = 0.f;
#pragma unroll
            for (int t = 0; t < 16; t++) {
                float e = __expf((vals[t] - m) * 0.125f);
                vals[t] = e;
                s += e;
            }
#pragma unroll
            for (int off = 16; off > 0; off >>= 1)
                s += __shfl_xor_sync(0xffffffffu, s, off);
            float inv = 1.0f / s;
#pragma unroll
            for (int t = 0; t < 16; t++)
                Ssm[r * 512 + lane + 32 * t] = vals[t] * inv;
        }
    }

    // ---- O[32][64] = P[32][512] @ V[512][64] ----
    float oacc[2][4] = {{0, 0, 0, 0}, {0, 0, 0, 0}};
    for (int kt = 0; kt < 8; kt++) {
        __syncthreads();   // also orders softmax writes before first read
        {
            int r = tid >> 4, c4 = (tid & 15) << 2;
#pragma unroll
            for (int p = 0; p < 4; p++) {
                float4 v = *(const float4*)(V + (size_t)(t0 + kt * 64 + r + 16 * p) * DDIM + hcol + c4);
                float* dst = &KVs[(r + 16 * p) * 65 + c4];
                dst[0] = v.x; dst[1] = v.y; dst[2] = v.z; dst[3] = v.w;
            }
        }
        __syncthreads();
#pragma unroll 8
        for (int j = 0; j < 64; j++) {
            float p0 = Ssm[r0 * 512 + kt * 64 + j];
            float p1 = Ssm[(r0 + 1) * 512 + kt * 64 + j];
#pragma unroll
            for (int u = 0; u < 4; u++) {
                float vv = KVs[j * 65 + j0 + u];
                oacc[0][u] = fmaf(p0, vv, oacc[0][u]);
                oacc[1][u] = fmaf(p1, vv, oacc[1][u]);
            }
        }
    }
#pragma unroll
    for (int i = 0; i < 2; i++) {
        size_t row = (size_t)(t0 + qbase + r0 + i);
#pragma unroll
        for (int u = 0; u < 4; u++)
            QC[row * DDIM + hcol + j0 + u] = oacc[i][u];
    }
}

// ---------------------------------------------------------------------------
// LayerNorm per row (1024 elems), keras eps = 1e-3. One block per row.
// ---------------------------------------------------------------------------
__global__ __launch_bounds__(256) void ln_kernel(
    const float* __restrict__ Y, const float* __restrict__ gamma,
    const float* __restrict__ beta, float* __restrict__ out)
{
    int row = blockIdx.x;
    int tid = threadIdx.x;
    const float* y = Y + (size_t)row * DDIM;

    float4 v = *(const float4*)(y + tid * 4);
    float s  = v.x + v.y + v.z + v.w;
    float sq = v.x * v.x + v.y * v.y + v.z * v.z + v.w * v.w;

#pragma unroll
    for (int off = 16; off > 0; off >>= 1) {
        s  += __shfl_xor_sync(0xffffffffu, s, off);
        sq += __shfl_xor_sync(0xffffffffu, sq, off);
    }
    __shared__ float ss[8], ssq[8];
    int lane = tid & 31, wid = tid >> 5;
    if (lane == 0) { ss[wid] = s; ssq[wid] = sq; }
    __syncthreads();
    float S = 0.f, SQ = 0.f;
#pragma unroll
    for (int i = 0; i < 8; i++) { S += ss[i]; SQ += ssq[i]; }

    float mu  = S * (1.0f / 1024.0f);
    float var = SQ * (1.0f / 1024.0f) - mu * mu;
    float inv = rsqrtf(var + 1e-3f);

    float4 g  = *(const float4*)(gamma + tid * 4);
    float4 be = *(const float4*)(beta + tid * 4);
    float4 o;
    o.x = (v.x - mu) * inv * g.x + be.x;
    o.y = (v.y - mu) * inv * g.y + be.y;
    o.z = (v.z - mu) * inv * g.z + be.z;
    o.w = (v.w - mu) * inv * g.w + be.w;
    *(float4*)(out + (size_t)row * DDIM + tid * 4) = o;
}

// ---------------------------------------------------------------------------
extern "C" void kernel_launch(void* const* d_in, const int* in_sizes, int n_in,
                              void* d_out, int out_size)
{
    const float* x     = (const float*)d_in[0];
    const float* Wq    = (const float*)d_in[1];
    const float* bq    = (const float*)d_in[2];
    const float* Wk    = (const float*)d_in[3];
    const float* bk    = (const float*)d_in[4];
    const float* Wv    = (const float*)d_in[5];
    const float* bv    = (const float*)d_in[6];
    const float* Wo    = (const float*)d_in[7];
    const float* bo    = (const float*)d_in[8];
    const float* gamma = (const float*)d_in[9];
    const float* beta  = (const float*)d_in[10];
    float* out = (float*)d_out;
    (void)in_sizes; (void)n_in; (void)out_size;

    float *Qp, *Kp, *Vp;
    cudaGetSymbolAddress((void**)&Qp, g_Q);
    cudaGetSymbolAddress((void**)&Kp, g_K);
    cudaGetSymbolAddress((void**)&Vp, g_V);

    const int ATTN_SMEM = 90496;
    cudaFuncSetAttribute(attn_kernel, cudaFuncAttributeMaxDynamicSharedMemorySize, ATTN_SMEM);

    dim3 gg(8, 128);  // (N/128, M/128)
    tf32_gemm_kernel<<<gg, 256>>>(x, Wq, bq, nullptr, Qp);
    tf32_gemm_kernel<<<gg, 256>>>(x, Wk, bk, nullptr, Kp);
    tf32_gemm_kernel<<<gg, 256>>>(x, Wv, bv, nullptr, Vp);

    // ctx overwrites Q in-place
    attn_kernel<<<dim3(16, 512), 256, ATTN_SMEM>>>(Kp, Vp, Qp);

    // Y = ctx @ Wo + bo + x   (write Y into g_K, dead after attention)
    tf32_gemm_kernel<<<gg, 256>>>(Qp, Wo, bo, x, Kp);

    ln_kernel<<<M_TOK, 256>>>(Kp, gamma, beta, out);
}

// round 5
// speedup vs baseline: 2.2000x; 1.4627x over previous
#include <cuda_runtime.h>
#include <math.h>
#include <stdint.h>

// Problem constants (fixed by the dataset instance)
#define M_TOK 16384   // B*S = 4*4096
#define DDIM  1024    // model dim = H*Khead = 16*64
// windows: 8 of 512 tokens; heads: 16 of dim 64

// Static device scratch (allocation-free rule): 3 x 64MB
__device__ float g_Q[(size_t)M_TOK * DDIM];
__device__ float g_K[(size_t)M_TOK * DDIM];
__device__ float g_V[(size_t)M_TOK * DDIM];

__device__ __forceinline__ float f2tf32(float x) {
    uint32_t u;
    asm("cvt.rna.tf32.f32 %0, %1;" : "=r"(u) : "f"(x));
    return __uint_as_float(u);
}

__device__ __forceinline__ void mma_tf32(
    float& d0, float& d1, float& d2, float& d3,
    uint32_t a0, uint32_t a1, uint32_t a2, uint32_t a3,
    uint32_t b0, uint32_t b1)
{
    asm volatile(
        "mma.sync.aligned.m16n8k8.row.col.f32.tf32.tf32.f32 "
        "{%0,%1,%2,%3}, {%4,%5,%6,%7}, {%8,%9}, {%0,%1,%2,%3};"
        : "+f"(d0), "+f"(d1), "+f"(d2), "+f"(d3)
        : "r"(a0), "r"(a1), "r"(a2), "r"(a3), "r"(b0), "r"(b1));
}

// ---------------------------------------------------------------------------
// TF32 tensor-core GEMM: C[M,1024] = A[M,1024] @ Bm[1024,1024] + bias[col]
// (+ resid). 128x128x32 block tile, 256 threads = 8 warps (4 m x 2 n).
// ---------------------------------------------------------------------------
__global__ __launch_bounds__(256) void tf32_gemm_kernel(
    const float* __restrict__ A, const float* __restrict__ Bm,
    const float* __restrict__ bias, const float* __restrict__ resid,
    float* __restrict__ C)
{
    __shared__ float As[128][36];
    __shared__ float Bs[32][136];

    int tid = threadIdx.x;
    int lane = tid & 31, wid = tid >> 5;
    int warp_m = wid & 3;
    int warp_n = wid >> 2;
    int gid = lane >> 2, tig = lane & 3;

    int row0 = blockIdx.y << 7;
    int col0 = blockIdx.x << 7;

    float acc[2][8][4];
#pragma unroll
    for (int mt = 0; mt < 2; mt++)
#pragma unroll
        for (int nt = 0; nt < 8; nt++)
#pragma unroll
            for (int r = 0; r < 4; r++) acc[mt][nt][r] = 0.f;

    int rowA = tid >> 1;
    int colA0 = (tid & 1) << 4;
    int rowB = tid >> 3;
    int colB0 = (tid & 7) << 4;

    const float* Ag = A + (size_t)(row0 + rowA) * DDIM + colA0;
    const float* Bg = Bm + (size_t)rowB * DDIM + col0 + colB0;

    for (int k0 = 0; k0 < DDIM; k0 += 32) {
        float4 av[4], bv[4];
#pragma unroll
        for (int p = 0; p < 4; p++) av[p] = *(const float4*)(Ag + k0 + p * 4);
#pragma unroll
        for (int p = 0; p < 4; p++) bv[p] = *(const float4*)(Bg + (size_t)k0 * DDIM + p * 4);

        __syncthreads();
#pragma unroll
        for (int p = 0; p < 4; p++) {
            float4 t;
            t.x = f2tf32(av[p].x); t.y = f2tf32(av[p].y);
            t.z = f2tf32(av[p].z); t.w = f2tf32(av[p].w);
            *(float4*)&As[rowA][colA0 + p * 4] = t;
            float4 u;
            u.x = f2tf32(bv[p].x); u.y = f2tf32(bv[p].y);
            u.z = f2tf32(bv[p].z); u.w = f2tf32(bv[p].w);
            *(float4*)&Bs[rowB][colB0 + p * 4] = u;
        }
        __syncthreads();

#pragma unroll
        for (int ks = 0; ks < 4; ks++) {
            int kk = ks << 3;
            uint32_t af[2][4];
            int mrow = (warp_m << 5) + gid;
#pragma unroll
            for (int mt = 0; mt < 2; mt++) {
                int r = mrow + (mt << 4);
                af[mt][0] = __float_as_uint(As[r][kk + tig]);
                af[mt][1] = __float_as_uint(As[r + 8][kk + tig]);
                af[mt][2] = __float_as_uint(As[r][kk + tig + 4]);
                af[mt][3] = __float_as_uint(As[r + 8][kk + tig + 4]);
            }
            uint32_t bf[8][2];
            int nbase = (warp_n << 6) + gid;
#pragma unroll
            for (int nt = 0; nt < 8; nt++) {
                int c = nbase + (nt << 3);
                bf[nt][0] = __float_as_uint(Bs[kk + tig][c]);
                bf[nt][1] = __float_as_uint(Bs[kk + tig + 4][c]);
            }
#pragma unroll
            for (int mt = 0; mt < 2; mt++)
#pragma unroll
                for (int nt = 0; nt < 8; nt++)
                    mma_tf32(acc[mt][nt][0], acc[mt][nt][1],
                             acc[mt][nt][2], acc[mt][nt][3],
                             af[mt][0], af[mt][1], af[mt][2], af[mt][3],
                             bf[nt][0], bf[nt][1]);
        }
    }

#pragma unroll
    for (int mt = 0; mt < 2; mt++) {
#pragma unroll
        for (int nt = 0; nt < 8; nt++) {
            int col = col0 + (warp_n << 6) + (nt << 3) + (tig << 1);
            float bx = bias[col], by = bias[col + 1];
#pragma unroll
            for (int h = 0; h < 2; h++) {
                size_t row = (size_t)row0 + (warp_m << 5) + (mt << 4) + gid + (h << 3);
                float2 o;
                o.x = acc[mt][nt][2 * h + 0] + bx;
                o.y = acc[mt][nt][2 * h + 1] + by;
                if (resid) {
                    float2 rv = *(const float2*)(resid + row * DDIM + col);
                    o.x += rv.x; o.y += rv.y;
                }
                *(float2*)(C + row * DDIM + col) = o;
            }
        }
    }
}

// ---------------------------------------------------------------------------
// Tensor-core windowed attention.
// Block = 64 q-rows of one (b,w,h) head; 512 threads = 16 warps.
// Warp w: key/d n-tile (w&7), m-group (w>>3) -> m-tiles {2*(w>>3), +1}.
// Phases: stage Q (tf32) -> QK^T mma into Ssm -> smem softmax (P stored
// tf32) -> PV mma -> store context in-place over Q.
// Smem: Ssm[64][516] + Qs[64][68] + KVs[64][68] = 166912 B.
// Padding analysis (bank = addr%32 words): 516%32=4, 68%32=4 ->
// QK-B / PV-A fragment loads conflict-free, PV-B worst 2-way.
// ---------------------------------------------------------------------------
#define SS_LD 516
#define QK_LD 68
#define ATTN_SMEM_BYTES ((64 * SS_LD + 64 * QK_LD + 64 * QK_LD) * 4)

__global__ __launch_bounds__(512) void attn_mma_kernel(
    const float* __restrict__ Km, const float* __restrict__ V,
    float* __restrict__ QC)   // Q in, context out (in-place)
{
    extern __shared__ float sm[];
    float* Ssm = sm;                       // [64][516]
    float* Qs  = sm + 64 * SS_LD;          // [64][68]
    float* KVs = Qs + 64 * QK_LD;          // [64][68]

    int tid = threadIdx.x;
    int lane = tid & 31;
    int w = tid >> 5;                      // 0..15
    int gid = lane >> 2, tig = lane & 3;
    int nt = w & 7;                        // n-tile (keys or d)
    int mg = w >> 3;                       // m-group: m-tiles 2mg, 2mg+1

    int hid = blockIdx.y;                  // (b, win, h)
    int b = hid >> 7;
    int wn = (hid >> 4) & 7;
    int h = hid & 15;
    int t0 = b * 4096 + wn * 512;
    int hcol = h << 6;
    int qbase = blockIdx.x << 6;           // 64 q-rows per block

    // ---- stage Q tile 64x64 (tf32) ----
    {
        int r = tid >> 3;
        int c0 = (tid & 7) << 3;
        const float* src = QC + (size_t)(t0 + qbase + r) * DDIM + hcol + c0;
        float4 v0 = *(const float4*)src;
        float4 v1 = *(const float4*)(src + 4);
        float* dst = &Qs[r * QK_LD + c0];
        dst[0] = f2tf32(v0.x); dst[1] = f2tf32(v0.y);
        dst[2] = f2tf32(v0.z); dst[3] = f2tf32(v0.w);
        dst[4] = f2tf32(v1.x); dst[5] = f2tf32(v1.y);
        dst[6] = f2tf32(v1.z); dst[7] = f2tf32(v1.w);
    }
    __syncthreads();

    // ---- hoist Q A-fragments (k-invariant across key tiles) ----
    uint32_t af[2][8][4];
#pragma unroll
    for (int mt = 0; mt < 2; mt++) {
        int mrow = ((mg << 1) + mt) << 4;
#pragma unroll
        for (int ks = 0; ks < 8; ks++) {
            int kk = ks << 3;
            af[mt][ks][0] = __float_as_uint(Qs[(mrow + gid) * QK_LD + kk + tig]);
            af[mt][ks][1] = __float_as_uint(Qs[(mrow + gid + 8) * QK_LD + kk + tig]);
            af[mt][ks][2] = __float_as_uint(Qs[(mrow + gid) * QK_LD + kk + tig + 4]);
            af[mt][ks][3] = __float_as_uint(Qs[(mrow + gid + 8) * QK_LD + kk + tig + 4]);
        }
    }

    // ---- scores S[64][512] = Q K^T via mma, tile 64 keys ----
    for (int kt = 0; kt < 8; kt++) {
        __syncthreads();
        {
            int r = tid >> 3;
            int c0 = (tid & 7) << 3;
            const float* src = Km + (size_t)(t0 + kt * 64 + r) * DDIM + hcol + c0;
            float4 v0 = *(const float4*)src;
            float4 v1 = *(const float4*)(src + 4);
            float* dst = &KVs[r * QK_LD + c0];
            dst[0] = f2tf32(v0.x); dst[1] = f2tf32(v0.y);
            dst[2] = f2tf32(v0.z); dst[3] = f2tf32(v0.w);
            dst[4] = f2tf32(v1.x); dst[5] = f2tf32(v1.y);
            dst[6] = f2tf32(v1.z); dst[7] = f2tf32(v1.w);
        }
        __syncthreads();

#pragma unroll
        for (int mt = 0; mt < 2; mt++) {
            float s0 = 0.f, s1 = 0.f, s2 = 0.f, s3 = 0.f;
#pragma unroll
            for (int ks = 0; ks < 8; ks++) {
                int kk = ks << 3;
                uint32_t b0 = __float_as_uint(KVs[((nt << 3) + gid) * QK_LD + kk + tig]);
                uint32_t b1 = __float_as_uint(KVs[((nt << 3) + gid) * QK_LD + kk + tig + 4]);
                mma_tf32(s0, s1, s2, s3,
                         af[mt][ks][0], af[mt][ks][1], af[mt][ks][2], af[mt][ks][3],
                         b0, b1);
            }
            int row = (((mg << 1) + mt) << 4) + gid;
            int col = kt * 64 + (nt << 3) + (tig << 1);
            *(float2*)&Ssm[row * SS_LD + col] = make_float2(s0, s1);
            *(float2*)&Ssm[(row + 8) * SS_LD + col] = make_float2(s2, s3);
        }
    }
    __syncthreads();

    // ---- softmax over 512 keys per row, scale 0.125; store P as tf32 ----
    {
#pragma unroll
        for (int q = 0; q < 4; q++) {
            int r = (w << 2) + q;
            float vals[16];
            float m = -1e30f;
#pragma unroll
            for (int t = 0; t < 16; t++) {
                vals[t] = Ssm[r * SS_LD + lane + 32 * t];
                m = fmaxf(m, vals[t]);
            }
#pragma unroll
            for (int off = 16; off > 0; off >>= 1)
                m = fmaxf(m, __shfl_xor_sync(0xffffffffu, m, off));
            float s = 0.f;
#pragma unroll
            for (int t = 0; t < 16; t++) {
                float e = __expf((vals[t] - m) * 0.125f);
                vals[t] = e;
                s += e;
            }
#pragma unroll
            for (int off = 16; off > 0; off >>= 1)
                s += __shfl_xor_sync(0xffffffffu, s, off);
            float inv = 1.0f / s;
#pragma unroll
            for (int t = 0; t < 16; t++)
                Ssm[r * SS_LD + lane + 32 * t] = f2tf32(vals[t] * inv);
        }
    }

    // ---- O[64][64] = P[64][512] @ V[512][64] via mma ----
    float oacc[2][4];
#pragma unroll
    for (int mt = 0; mt < 2; mt++)
#pragma unroll
        for (int r = 0; r < 4; r++) oacc[mt][r] = 0.f;

    for (int kt = 0; kt < 8; kt++) {
        __syncthreads();   // also orders softmax writes before first read
        {
            int r = tid >> 3;
            int c0 = (tid & 7) << 3;
            const float* src = V + (size_t)(t0 + kt * 64 + r) * DDIM + hcol + c0;
            float4 v0 = *(const float4*)src;
            float4 v1 = *(const float4*)(src + 4);
            float* dst = &KVs[r * QK_LD + c0];
            dst[0] = f2tf32(v0.x); dst[1] = f2tf32(v0.y);
            dst[2] = f2tf32(v0.z); dst[3] = f2tf32(v0.w);
            dst[4] = f2tf32(v1.x); dst[5] = f2tf32(v1.y);
            dst[6] = f2tf32(v1.z); dst[7] = f2tf32(v1.w);
        }
        __syncthreads();

#pragma unroll
        for (int ks = 0; ks < 8; ks++) {
            int kk = ks << 3;
            uint32_t b0 = __float_as_uint(KVs[(kk + tig) * QK_LD + (nt << 3) + gid]);
            uint32_t b1 = __float_as_uint(KVs[(kk + tig + 4) * QK_LD + (nt << 3) + gid]);
#pragma unroll
            for (int mt = 0; mt < 2; mt++) {
                int mrow = (((mg << 1) + mt) << 4);
                int kc = kt * 64 + kk;
                uint32_t a0 = __float_as_uint(Ssm[(mrow + gid) * SS_LD + kc + tig]);
                uint32_t a1 = __float_as_uint(Ssm[(mrow + gid + 8) * SS_LD + kc + tig]);
                uint32_t a2 = __float_as_uint(Ssm[(mrow + gid) * SS_LD + kc + tig + 4]);
                uint32_t a3 = __float_as_uint(Ssm[(mrow + gid + 8) * SS_LD + kc + tig + 4]);
                mma_tf32(oacc[mt][0], oacc[mt][1], oacc[mt][2], oacc[mt][3],
                         a0, a1, a2, a3, b0, b1);
            }
        }
    }

    // ---- store context in-place over Q ----
#pragma unroll
    for (int mt = 0; mt < 2; mt++) {
        size_t row = (size_t)t0 + qbase + (((mg << 1) + mt) << 4) + gid;
        int col = hcol + (nt << 3) + (tig << 1);
        *(float2*)(QC + row * DDIM + col) = make_float2(oacc[mt][0], oacc[mt][1]);
        *(float2*)(QC + (row + 8) * DDIM + col) = make_float2(oacc[mt][2], oacc[mt][3]);
    }
}

// ---------------------------------------------------------------------------
// LayerNorm per row (1024 elems), keras eps = 1e-3. One block per row.
// ---------------------------------------------------------------------------
__global__ __launch_bounds__(256) void ln_kernel(
    const float* __restrict__ Y, const float* __restrict__ gamma,
    const float* __restrict__ beta, float* __restrict__ out)
{
    int row = blockIdx.x;
    int tid = threadIdx.x;
    const float* y = Y + (size_t)row * DDIM;

    float4 v = *(const float4*)(y + tid * 4);
    float s  = v.x + v.y + v.z + v.w;
    float sq = v.x * v.x + v.y * v.y + v.z * v.z + v.w * v.w;

#pragma unroll
    for (int off = 16; off > 0; off >>= 1) {
        s  += __shfl_xor_sync(0xffffffffu, s, off);
        sq += __shfl_xor_sync(0xffffffffu, sq, off);
    }
    __shared__ float ss[8], ssq[8];
    int lane = tid & 31, wid = tid >> 5;
    if (lane == 0) { ss[wid] = s; ssq[wid] = sq; }
    __syncthreads();
    float S = 0.f, SQ = 0.f;
#pragma unroll
    for (int i = 0; i < 8; i++) { S += ss[i]; SQ += ssq[i]; }

    float mu  = S * (1.0f / 1024.0f);
    float var = SQ * (1.0f / 1024.0f) - mu * mu;
    float inv = rsqrtf(var + 1e-3f);

    float4 g  = *(const float4*)(gamma + tid * 4);
    float4 be = *(const float4*)(beta + tid * 4);
    float4 o;
    o.x = (v.x - mu) * inv * g.x + be.x;
    o.y = (v.y - mu) * inv * g.y + be.y;
    o.z = (v.z - mu) * inv * g.z + be.z;
    o.w = (v.w - mu) * inv * g.w + be.w;
    *(float4*)(out + (size_t)row * DDIM + tid * 4) = o;
}

// ---------------------------------------------------------------------------
extern "C" void kernel_launch(void* const* d_in, const int* in_sizes, int n_in,
                              void* d_out, int out_size)
{
    const float* x     = (const float*)d_in[0];
    const float* Wq    = (const float*)d_in[1];
    const float* bq    = (const float*)d_in[2];
    const float* Wk    = (const float*)d_in[3];
    const float* bk    = (const float*)d_in[4];
    const float* Wv    = (const float*)d_in[5];
    const float* bv    = (const float*)d_in[6];
    const float* Wo    = (const float*)d_in[7];
    const float* bo    = (const float*)d_in[8];
    const float* gamma = (const float*)d_in[9];
    const float* beta  = (const float*)d_in[10];
    float* out = (float*)d_out;
    (void)in_sizes; (void)n_in; (void)out_size;

    float *Qp, *Kp, *Vp;
    cudaGetSymbolAddress((void**)&Qp, g_Q);
    cudaGetSymbolAddress((void**)&Kp, g_K);
    cudaGetSymbolAddress((void**)&Vp, g_V);

    cudaFuncSetAttribute(attn_mma_kernel,
                         cudaFuncAttributeMaxDynamicSharedMemorySize, ATTN_SMEM_BYTES);

    dim3 gg(8, 128);  // (N/128, M/128)
    tf32_gemm_kernel<<<gg, 256>>>(x, Wq, bq, nullptr, Qp);
    tf32_gemm_kernel<<<gg, 256>>>(x, Wk, bk, nullptr, Kp);
    tf32_gemm_kernel<<<gg, 256>>>(x, Wv, bv, nullptr, Vp);

    // ctx overwrites Q in-place; grid: 8 q-tiles of 64 x 512 heads
    attn_mma_kernel<<<dim3(8, 512), 512, ATTN_SMEM_BYTES>>>(Kp, Vp, Qp);

    // Y = ctx @ Wo + bo + x   (write Y into g_K, dead after attention)
    tf32_gemm_kernel<<<gg, 256>>>(Qp, Wo, bo, x, Kp);

    ln_kernel<<<M_TOK, 256>>>(Kp, gamma, beta, out);
}

// round 8
// speedup vs baseline: 2.6381x; 1.1991x over previous
#include <cuda_runtime.h>
#include <math.h>
#include <stdint.h>

// Problem constants (fixed by the dataset instance)
#define M_TOK 16384   // B*S = 4*4096
#define DDIM  1024    // model dim = H*Khead = 16*64
// windows: 8 of 512 tokens; heads: 16 of dim 64

// Static device scratch (allocation-free rule): 3 x 64MB
__device__ float g_Q[(size_t)M_TOK * DDIM];
__device__ float g_K[(size_t)M_TOK * DDIM];
__device__ float g_V[(size_t)M_TOK * DDIM];

// Raw fp32 fed to tf32 MMA == truncation to tf32 (HW ignores low mantissa
// bits). Saves the cvt + register bounce; error stays ~1e-4 << 1e-3.
__device__ __forceinline__ void mma_tf32(
    float& d0, float& d1, float& d2, float& d3,
    uint32_t a0, uint32_t a1, uint32_t a2, uint32_t a3,
    uint32_t b0, uint32_t b1)
{
    asm volatile(
        "mma.sync.aligned.m16n8k8.row.col.f32.tf32.tf32.f32 "
        "{%0,%1,%2,%3}, {%4,%5,%6,%7}, {%8,%9}, {%0,%1,%2,%3};"
        : "+f"(d0), "+f"(d1), "+f"(d2), "+f"(d3)
        : "r"(a0), "r"(a1), "r"(a2), "r"(a3), "r"(b0), "r"(b1));
}

__device__ __forceinline__ void cp_async16(void* smem_dst, const void* gsrc) {
    uint32_t s = (uint32_t)__cvta_generic_to_shared(smem_dst);
    asm volatile("cp.async.cg.shared.global [%0], [%1], 16;" :: "r"(s), "l"(gsrc));
}
__device__ __forceinline__ void cp_commit() {
    asm volatile("cp.async.commit_group;");
}
__device__ __forceinline__ void cp_wait_all() {
    asm volatile("cp.async.wait_group 0;");
}

// ---------------------------------------------------------------------------
// TF32 tensor-core GEMM: C[M,1024] = A[M,1024] @ Bm[1024,1024] + bias[col]
// (+ resid). 128x128x32 block tile, 256 threads = 8 warps (4 m x 2 n).
// 2-stage cp.async pipeline: prefetch tile t+1 while computing tile t.
// dyn smem: 2*(128*36 + 32*136)*4 = 71680 B
// ---------------------------------------------------------------------------
#define GEMM_SMEM_BYTES ((2 * 128 * 36 + 2 * 32 * 136) * 4)

__global__ __launch_bounds__(256) void tf32_gemm_kernel(
    const float* __restrict__ A, const float* __restrict__ Bm,
    const float* __restrict__ bias, const float* __restrict__ resid,
    float* __restrict__ C)
{
    extern __shared__ float gsm[];
    float (*As)[128][36] = (float(*)[128][36])gsm;               // [2][128][36]
    float (*Bs)[32][136] = (float(*)[32][136])(gsm + 2 * 128 * 36);

    int tid = threadIdx.x;
    int lane = tid & 31, wid = tid >> 5;
    int warp_m = wid & 3;
    int warp_n = wid >> 2;
    int gid = lane >> 2, tig = lane & 3;

    int row0 = blockIdx.y << 7;
    int col0 = blockIdx.x << 7;

    float acc[2][8][4];
#pragma unroll
    for (int mt = 0; mt < 2; mt++)
#pragma unroll
        for (int nt = 0; nt < 8; nt++)
#pragma unroll
            for (int r = 0; r < 4; r++) acc[mt][nt][r] = 0.f;

    int rowA = tid >> 1;
    int colA0 = (tid & 1) << 4;        // 0 or 16 floats
    int rowB = tid >> 3;
    int colB0 = (tid & 7) << 4;        // 0..112 step 16

    const float* Ag = A + (size_t)(row0 + rowA) * DDIM + colA0;
    const float* Bg = Bm + (size_t)rowB * DDIM + col0 + colB0;

    // preamble: stage tile 0
#pragma unroll
    for (int p = 0; p < 4; p++) {
        cp_async16(&As[0][rowA][colA0 + p * 4], Ag + p * 4);
        cp_async16(&Bs[0][rowB][colB0 + p * 4], Bg + p * 4);
    }
    cp_commit();
    cp_wait_all();
    __syncthreads();

    for (int t = 0; t < 32; t++) {
        if (t < 31) {
            int sn = (t + 1) & 1;
            int k0n = (t + 1) << 5;
#pragma unroll
            for (int p = 0; p < 4; p++) {
                cp_async16(&As[sn][rowA][colA0 + p * 4], Ag + k0n + p * 4);
                cp_async16(&Bs[sn][rowB][colB0 + p * 4],
                           Bg + (size_t)k0n * DDIM + p * 4);
            }
            cp_commit();
        }

        int s = t & 1;
#pragma unroll
        for (int ks = 0; ks < 4; ks++) {
            int kk = ks << 3;
            uint32_t af[2][4];
            int mrow = (warp_m << 5) + gid;
#pragma unroll
            for (int mt = 0; mt < 2; mt++) {
                int r = mrow + (mt << 4);
                af[mt][0] = __float_as_uint(As[s][r][kk + tig]);
                af[mt][1] = __float_as_uint(As[s][r + 8][kk + tig]);
                af[mt][2] = __float_as_uint(As[s][r][kk + tig + 4]);
                af[mt][3] = __float_as_uint(As[s][r + 8][kk + tig + 4]);
            }
            uint32_t bf[8][2];
            int nbase = (warp_n << 6) + gid;
#pragma unroll
            for (int nt = 0; nt < 8; nt++) {
                int c = nbase + (nt << 3);
                bf[nt][0] = __float_as_uint(Bs[s][kk + tig][c]);
                bf[nt][1] = __float_as_uint(Bs[s][kk + tig + 4][c]);
            }
#pragma unroll
            for (int mt = 0; mt < 2; mt++)
#pragma unroll
                for (int nt = 0; nt < 8; nt++)
                    mma_tf32(acc[mt][nt][0], acc[mt][nt][1],
                             acc[mt][nt][2], acc[mt][nt][3],
                             af[mt][0], af[mt][1], af[mt][2], af[mt][3],
                             bf[nt][0], bf[nt][1]);
        }
        cp_wait_all();
        __syncthreads();
    }

#pragma unroll
    for (int mt = 0; mt < 2; mt++) {
#pragma unroll
        for (int nt = 0; nt < 8; nt++) {
            int col = col0 + (warp_n << 6) + (nt << 3) + (tig << 1);
            float bx = bias[col], by = bias[col + 1];
#pragma unroll
            for (int h = 0; h < 2; h++) {
                size_t row = (size_t)row0 + (warp_m << 5) + (mt << 4) + gid + (h << 3);
                float2 o;
                o.x = acc[mt][nt][2 * h + 0] + bx;
                o.y = acc[mt][nt][2 * h + 1] + by;
                if (resid) {
                    float2 rv = *(const float2*)(resid + row * DDIM + col);
                    o.x += rv.x; o.y += rv.y;
                }
                *(float2*)(C + row * DDIM + col) = o;
            }
        }
    }
}

// ---------------------------------------------------------------------------
// Tensor-core windowed attention, cp.async double-buffered K/V tiles.
// Block = 64 q-rows of one (b,w,h) head; 512 threads = 16 warps.
// Warp w: n-tile (w&7), m-group (w>>3). All operands raw fp32 (tf32 trunc).
// Smem: Ssm[64][516] + Qs[64][68] + KVs[2][64][68] = 184320 B.
// ---------------------------------------------------------------------------
#define SS_LD 516
#define QK_LD 68
#define ATTN_SMEM_BYTES ((64 * SS_LD + 64 * QK_LD + 2 * 64 * QK_LD) * 4)

__global__ __launch_bounds__(512) void attn_mma_kernel(
    const float* __restrict__ Km, const float* __restrict__ V,
    float* __restrict__ QC)   // Q in, context out (in-place)
{
    extern __shared__ float sm[];
    float* Ssm = sm;                        // [64][516]
    float* Qs  = sm + 64 * SS_LD;           // [64][68]
    float* KV0 = Qs + 64 * QK_LD;           // [64][68] stage 0
    float* KV1 = KV0 + 64 * QK_LD;          // [64][68] stage 1

    int tid = threadIdx.x;
    int lane = tid & 31;
    int w = tid >> 5;
    int gid = lane >> 2, tig = lane & 3;
    int nt = w & 7;
    int mg = w >> 3;

    int hid = blockIdx.y;                   // (b, win, h)
    int b = hid >> 7;
    int wn = (hid >> 4) & 7;
    int h = hid & 15;
    int t0 = b * 4096 + wn * 512;
    int hcol = h << 6;
    int qbase = blockIdx.x << 6;

    int r = tid >> 3;                       // 0..63 staging row
    int c0 = (tid & 7) << 3;                // 0..56 staging col (8 floats)

    // ---- stage Q tile 64x64 (raw) + prefetch K tile 0 ----
    {
        const float* src = QC + (size_t)(t0 + qbase + r) * DDIM + hcol + c0;
        float4 v0 = *(const float4*)src;
        float4 v1 = *(const float4*)(src + 4);
        *(float4*)&Qs[r * QK_LD + c0] = v0;
        *(float4*)&Qs[r * QK_LD + c0 + 4] = v1;
    }
    {
        const float* src = Km + (size_t)(t0 + r) * DDIM + hcol + c0;
        cp_async16(&KV0[r * QK_LD + c0], src);
        cp_async16(&KV0[r * QK_LD + c0 + 4], src + 4);
        cp_commit();
    }
    cp_wait_all();
    __syncthreads();

    // ---- hoist Q A-fragments (k-invariant across key tiles) ----
    uint32_t af[2][8][4];
#pragma unroll
    for (int mt = 0; mt < 2; mt++) {
        int mrow = ((mg << 1) + mt) << 4;
#pragma unroll
        for (int ks = 0; ks < 8; ks++) {
            int kk = ks << 3;
            af[mt][ks][0] = __float_as_uint(Qs[(mrow + gid) * QK_LD + kk + tig]);
            af[mt][ks][1] = __float_as_uint(Qs[(mrow + gid + 8) * QK_LD + kk + tig]);
            af[mt][ks][2] = __float_as_uint(Qs[(mrow + gid) * QK_LD + kk + tig + 4]);
            af[mt][ks][3] = __float_as_uint(Qs[(mrow + gid + 8) * QK_LD + kk + tig + 4]);
        }
    }

    // ---- scores S[64][512] = Q K^T via mma, pipelined over 8 key tiles ----
    for (int kt = 0; kt < 8; kt++) {
        float* cur = (kt & 1) ? KV1 : KV0;
        if (kt < 7) {
            float* nxt = (kt & 1) ? KV0 : KV1;
            const float* src = Km + (size_t)(t0 + (kt + 1) * 64 + r) * DDIM + hcol + c0;
            cp_async16(&nxt[r * QK_LD + c0], src);
            cp_async16(&nxt[r * QK_LD + c0 + 4], src + 4);
            cp_commit();
        }
#pragma unroll
        for (int mt = 0; mt < 2; mt++) {
            float s0 = 0.f, s1 = 0.f, s2 = 0.f, s3 = 0.f;
#pragma unroll
            for (int ks = 0; ks < 8; ks++) {
                int kk = ks << 3;
                uint32_t b0 = __float_as_uint(cur[((nt << 3) + gid) * QK_LD + kk + tig]);
                uint32_t b1 = __float_as_uint(cur[((nt << 3) + gid) * QK_LD + kk + tig + 4]);
                mma_tf32(s0, s1, s2, s3,
                         af[mt][ks][0], af[mt][ks][1], af[mt][ks][2], af[mt][ks][3],
                         b0, b1);
            }
            int row = (((mg << 1) + mt) << 4) + gid;
            int col = kt * 64 + (nt << 3) + (tig << 1);
            *(float2*)&Ssm[row * SS_LD + col] = make_float2(s0, s1);
            *(float2*)&Ssm[(row + 8) * SS_LD + col] = make_float2(s2, s3);
        }
        cp_wait_all();
        __syncthreads();
    }

    // prefetch V tile 0 (both KV buffers free), overlaps softmax
    {
        const float* src = V + (size_t)(t0 + r) * DDIM + hcol + c0;
        cp_async16(&KV0[r * QK_LD + c0], src);
        cp_async16(&KV0[r * QK_LD + c0 + 4], src + 4);
        cp_commit();
    }

    // ---- softmax over 512 keys per row, scale 0.125 (P stored raw) ----
    {
#pragma unroll
        for (int q = 0; q < 4; q++) {
            int rr = (w << 2) + q;
            float vals[16];
            float m = -1e30f;
#pragma unroll
            for (int t = 0; t < 16; t++) {
                vals[t] = Ssm[rr * SS_LD + lane + 32 * t];
                m = fmaxf(m, vals[t]);
            }
#pragma unroll
            for (int off = 16; off > 0; off >>= 1)
                m = fmaxf(m, __shfl_xor_sync(0xffffffffu, m, off));
            float s = 0.f;
#pragma unroll
            for (int t = 0; t < 16; t++) {
                float e = __expf((vals[t] - m) * 0.125f);
                vals[t] = e;
                s += e;
            }
#pragma unroll
            for (int off = 16; off > 0; off >>= 1)
                s += __shfl_xor_sync(0xffffffffu, s, off);
            float inv = 1.0f / s;
#pragma unroll
            for (int t = 0; t < 16; t++)
                Ssm[rr * SS_LD + lane + 32 * t] = vals[t] * inv;
        }
    }
    cp_wait_all();
    __syncthreads();   // V0 ready; softmax writes visible

    // ---- O[64][64] = P[64][512] @ V[512][64], pipelined ----
    float oacc[2][4];
#pragma unroll
    for (int mt = 0; mt < 2; mt++)
#pragma unroll
        for (int q = 0; q < 4; q++) oacc[mt][q] = 0.f;

    for (int kt = 0; kt < 8; kt++) {
        float* cur = (kt & 1) ? KV1 : KV0;
        if (kt < 7) {
            float* nxt = (kt & 1) ? KV0 : KV1;
            const float* src = V + (size_t)(t0 + (kt + 1) * 64 + r) * DDIM + hcol + c0;
            cp_async16(&nxt[r * QK_LD + c0], src);
            cp_async16(&nxt[r * QK_LD + c0 + 4], src + 4);
            cp_commit();
        }
#pragma unroll
        for (int ks = 0; ks < 8; ks++) {
            int kk = ks << 3;
            uint32_t b0 = __float_as_uint(cur[(kk + tig) * QK_LD + (nt << 3) + gid]);
            uint32_t b1 = __float_as_uint(cur[(kk + tig + 4) * QK_LD + (nt << 3) + gid]);
#pragma unroll
            for (int mt = 0; mt < 2; mt++) {
                int mrow = (((mg << 1) + mt) << 4);
                int kc = kt * 64 + kk;
                uint32_t a0 = __float_as_uint(Ssm[(mrow + gid) * SS_LD + kc + tig]);
                uint32_t a1 = __float_as_uint(Ssm[(mrow + gid + 8) * SS_LD + kc + tig]);
                uint32_t a2 = __float_as_uint(Ssm[(mrow + gid) * SS_LD + kc + tig + 4]);
                uint32_t a3 = __float_as_uint(Ssm[(mrow + gid + 8) * SS_LD + kc + tig + 4]);
                mma_tf32(oacc[mt][0], oacc[mt][1], oacc[mt][2], oacc[mt][3],
                         a0, a1, a2, a3, b0, b1);
            }
        }
        cp_wait_all();
        __syncthreads();
    }

    // ---- store context in-place over Q ----
#pragma unroll
    for (int mt = 0; mt < 2; mt++) {
        size_t row = (size_t)t0 + qbase + (((mg << 1) + mt) << 4) + gid;
        int col = hcol + (nt << 3) + (tig << 1);
        *(float2*)(QC + row * DDIM + col) = make_float2(oacc[mt][0], oacc[mt][1]);
        *(float2*)(QC + (row + 8) * DDIM + col) = make_float2(oacc[mt][2], oacc[mt][3]);
    }
}

// ---------------------------------------------------------------------------
// LayerNorm per row (1024 elems), keras eps = 1e-3. One block per row.
// ---------------------------------------------------------------------------
__global__ __launch_bounds__(256) void ln_kernel(
    const float* __restrict__ Y, const float* __restrict__ gamma,
    const float* __restrict__ beta, float* __restrict__ out)
{
    int row = blockIdx.x;
    int tid = threadIdx.x;
    const float* y = Y + (size_t)row * DDIM;

    float4 v = *(const float4*)(y + tid * 4);
    float s  = v.x + v.y + v.z + v.w;
    float sq = v.x * v.x + v.y * v.y + v.z * v.z + v.w * v.w;

#pragma unroll
    for (int off = 16; off > 0; off >>= 1) {
        s  += __shfl_xor_sync(0xffffffffu, s, off);
        sq += __shfl_xor_sync(0xffffffffu, sq, off);
    }
    __shared__ float ss[8], ssq[8];
    int lane = tid & 31, wid = tid >> 5;
    if (lane == 0) { ss[wid] = s; ssq[wid] = sq; }
    __syncthreads();
    float S = 0.f, SQ = 0.f;
#pragma unroll
    for (int i = 0; i < 8; i++) { S += ss[i]; SQ += ssq[i]; }

    float mu  = S * (1.0f / 1024.0f);
    float var = SQ * (1.0f / 1024.0f) - mu * mu;
    float inv = rsqrtf(var + 1e-3f);

    float4 g  = *(const float4*)(gamma + tid * 4);
    float4 be = *(const float4*)(beta + tid * 4);
    float4 o;
    o.x = (v.x - mu) * inv * g.x + be.x;
    o.y = (v.y - mu) * inv * g.y + be.y;
    o.z = (v.z - mu) * inv * g.z + be.z;
    o.w = (v.w - mu) * inv * g.w + be.w;
    *(float4*)(out + (size_t)row * DDIM + tid * 4) = o;
}

// ---------------------------------------------------------------------------
extern "C" void kernel_launch(void* const* d_in, const int* in_sizes, int n_in,
                              void* d_out, int out_size)
{
    const float* x     = (const float*)d_in[0];
    const float* Wq    = (const float*)d_in[1];
    const float* bq    = (const float*)d_in[2];
    const float* Wk    = (const float*)d_in[3];
    const float* bk    = (const float*)d_in[4];
    const float* Wv    = (const float*)d_in[5];
    const float* bv    = (const float*)d_in[6];
    const float* Wo    = (const float*)d_in[7];
    const float* bo    = (const float*)d_in[8];
    const float* gamma = (const float*)d_in[9];
    const float* beta  = (const float*)d_in[10];
    float* out = (float*)d_out;
    (void)in_sizes; (void)n_in; (void)out_size;

    float *Qp, *Kp, *Vp;
    cudaGetSymbolAddress((void**)&Qp, g_Q);
    cudaGetSymbolAddress((void**)&Kp, g_K);
    cudaGetSymbolAddress((void**)&Vp, g_V);

    cudaFuncSetAttribute(tf32_gemm_kernel,
                         cudaFuncAttributeMaxDynamicSharedMemorySize, GEMM_SMEM_BYTES);
    cudaFuncSetAttribute(attn_mma_kernel,
                         cudaFuncAttributeMaxDynamicSharedMemorySize, ATTN_SMEM_BYTES);

    dim3 gg(8, 128);  // (N/128, M/128)
    tf32_gemm_kernel<<<gg, 256, GEMM_SMEM_BYTES>>>(x, Wq, bq, nullptr, Qp);
    tf32_gemm_kernel<<<gg, 256, GEMM_SMEM_BYTES>>>(x, Wk, bk, nullptr, Kp);
    tf32_gemm_kernel<<<gg, 256, GEMM_SMEM_BYTES>>>(x, Wv, bv, nullptr, Vp);

    // ctx overwrites Q in-place; grid: 8 q-tiles of 64 x 512 heads
    attn_mma_kernel<<<dim3(8, 512), 512, ATTN_SMEM_BYTES>>>(Kp, Vp, Qp);

    // Y = ctx @ Wo + bo + x   (write Y into g_K, dead after attention)
    tf32_gemm_kernel<<<gg, 256, GEMM_SMEM_BYTES>>>(Qp, Wo, bo, x, Kp);

    ln_kernel<<<M_TOK, 256>>>(Kp, gamma, beta, out);
}

// round 11
// speedup vs baseline: 2.7068x; 1.0260x over previous
#include <cuda_runtime.h>
#include <math.h>
#include <stdint.h>

// Problem constants (fixed by the dataset instance)
#define M_TOK 16384   // B*S = 4*4096
#define DDIM  1024    // model dim = H*Khead = 16*64
// windows: 8 of 512 tokens; heads: 16 of dim 64

// Static device scratch (allocation-free rule): 3 x 64MB
__device__ float g_Q[(size_t)M_TOK * DDIM];
__device__ float g_K[(size_t)M_TOK * DDIM];
__device__ float g_V[(size_t)M_TOK * DDIM];

// Raw fp32 fed to tf32 MMA == truncation to tf32 (HW ignores low mantissa
// bits).
__device__ __forceinline__ void mma_tf32(
    float& d0, float& d1, float& d2, float& d3,
    uint32_t a0, uint32_t a1, uint32_t a2, uint32_t a3,
    uint32_t b0, uint32_t b1)
{
    asm volatile(
        "mma.sync.aligned.m16n8k8.row.col.f32.tf32.tf32.f32 "
        "{%0,%1,%2,%3}, {%4,%5,%6,%7}, {%8,%9}, {%0,%1,%2,%3};"
        : "+f"(d0), "+f"(d1), "+f"(d2), "+f"(d3)
        : "r"(a0), "r"(a1), "r"(a2), "r"(a3), "r"(b0), "r"(b1));
}

__device__ __forceinline__ void cp_async16(void* smem_dst, const void* gsrc) {
    uint32_t s = (uint32_t)__cvta_generic_to_shared(smem_dst);
    asm volatile("cp.async.cg.shared.global [%0], [%1], 16;" :: "r"(s), "l"(gsrc));
}
__device__ __forceinline__ void cp_commit() {
    asm volatile("cp.async.commit_group;");
}
__device__ __forceinline__ void cp_wait_all() {
    asm volatile("cp.async.wait_group 0;");
}

// ---------------------------------------------------------------------------
// TF32 tensor-core GEMM, 3-output variant: z = blockIdx.z selects (Bm, bias,
// C). C[M,1024] = A[M,1024] @ Bm[1024,1024] + bias (+ resid).
// 128x128x32 block tile, 256 threads = 8 warps (4 m x 2 n).
// 2-stage cp.async pipeline. dyn smem: 2*(128*36 + 32*136)*4 = 71680 B
// ---------------------------------------------------------------------------
#define GEMM_SMEM_BYTES ((2 * 128 * 36 + 2 * 32 * 136) * 4)

__global__ __launch_bounds__(256) void tf32_gemm3_kernel(
    const float* __restrict__ A,
    const float* __restrict__ B0, const float* __restrict__ B1,
    const float* __restrict__ B2,
    const float* __restrict__ bias0, const float* __restrict__ bias1,
    const float* __restrict__ bias2,
    const float* __restrict__ resid,
    float* __restrict__ C0, float* __restrict__ C1, float* __restrict__ C2)
{
    extern __shared__ float gsm[];
    float (*As)[128][36] = (float(*)[128][36])gsm;               // [2][128][36]
    float (*Bs)[32][136] = (float(*)[32][136])(gsm + 2 * 128 * 36);

    int z = blockIdx.z;
    const float* Bm   = (z == 0) ? B0 : (z == 1) ? B1 : B2;
    const float* bias = (z == 0) ? bias0 : (z == 1) ? bias1 : bias2;
    float* C          = (z == 0) ? C0 : (z == 1) ? C1 : C2;

    int tid = threadIdx.x;
    int lane = tid & 31, wid = tid >> 5;
    int warp_m = wid & 3;
    int warp_n = wid >> 2;
    int gid = lane >> 2, tig = lane & 3;

    int row0 = blockIdx.y << 7;
    int col0 = blockIdx.x << 7;

    float acc[2][8][4];
#pragma unroll
    for (int mt = 0; mt < 2; mt++)
#pragma unroll
        for (int nt = 0; nt < 8; nt++)
#pragma unroll
            for (int r = 0; r < 4; r++) acc[mt][nt][r] = 0.f;

    int rowA = tid >> 1;
    int colA0 = (tid & 1) << 4;        // 0 or 16 floats
    int rowB = tid >> 3;
    int colB0 = (tid & 7) << 4;        // 0..112 step 16

    const float* Ag = A + (size_t)(row0 + rowA) * DDIM + colA0;
    const float* Bg = Bm + (size_t)rowB * DDIM + col0 + colB0;

    // preamble: stage tile 0
#pragma unroll
    for (int p = 0; p < 4; p++) {
        cp_async16(&As[0][rowA][colA0 + p * 4], Ag + p * 4);
        cp_async16(&Bs[0][rowB][colB0 + p * 4], Bg + p * 4);
    }
    cp_commit();
    cp_wait_all();
    __syncthreads();

    for (int t = 0; t < 32; t++) {
        if (t < 31) {
            int sn = (t + 1) & 1;
            int k0n = (t + 1) << 5;
#pragma unroll
            for (int p = 0; p < 4; p++) {
                cp_async16(&As[sn][rowA][colA0 + p * 4], Ag + k0n + p * 4);
                cp_async16(&Bs[sn][rowB][colB0 + p * 4],
                           Bg + (size_t)k0n * DDIM + p * 4);
            }
            cp_commit();
        }

        int s = t & 1;
#pragma unroll
        for (int ks = 0; ks < 4; ks++) {
            int kk = ks << 3;
            uint32_t af[2][4];
            int mrow = (warp_m << 5) + gid;
#pragma unroll
            for (int mt = 0; mt < 2; mt++) {
                int r = mrow + (mt << 4);
                af[mt][0] = __float_as_uint(As[s][r][kk + tig]);
                af[mt][1] = __float_as_uint(As[s][r + 8][kk + tig]);
                af[mt][2] = __float_as_uint(As[s][r][kk + tig + 4]);
                af[mt][3] = __float_as_uint(As[s][r + 8][kk + tig + 4]);
            }
            uint32_t bf[8][2];
            int nbase = (warp_n << 6) + gid;
#pragma unroll
            for (int nt = 0; nt < 8; nt++) {
                int c = nbase + (nt << 3);
                bf[nt][0] = __float_as_uint(Bs[s][kk + tig][c]);
                bf[nt][1] = __float_as_uint(Bs[s][kk + tig + 4][c]);
            }
#pragma unroll
            for (int mt = 0; mt < 2; mt++)
#pragma unroll
                for (int nt = 0; nt < 8; nt++)
                    mma_tf32(acc[mt][nt][0], acc[mt][nt][1],
                             acc[mt][nt][2], acc[mt][nt][3],
                             af[mt][0], af[mt][1], af[mt][2], af[mt][3],
                             bf[nt][0], bf[nt][1]);
        }
        cp_wait_all();
        __syncthreads();
    }

#pragma unroll
    for (int mt = 0; mt < 2; mt++) {
#pragma unroll
        for (int nt = 0; nt < 8; nt++) {
            int col = col0 + (warp_n << 6) + (nt << 3) + (tig << 1);
            float bx = bias[col], by = bias[col + 1];
#pragma unroll
            for (int h = 0; h < 2; h++) {
                size_t row = (size_t)row0 + (warp_m << 5) + (mt << 4) + gid + (h << 3);
                float2 o;
                o.x = acc[mt][nt][2 * h + 0] + bx;
                o.y = acc[mt][nt][2 * h + 1] + by;
                if (resid) {
                    float2 rv = *(const float2*)(resid + row * DDIM + col);
                    o.x += rv.x; o.y += rv.y;
                }
                *(float2*)(C + row * DDIM + col) = o;
            }
        }
    }
}

// ---------------------------------------------------------------------------
// Tensor-core windowed attention, 32 q-rows per block for 2 CTAs/SM.
// 512 threads = 16 warps: warp w -> n-tile (w&7), m-tile mg=(w>>3) (16 rows).
// Q staging tile overlays KV stage-1 buffer (consumed into af regs before
// that buffer's first prefetch).
// Smem: Ssm[32][516] + KV[2][64][68] = 100864 B -> 2 blocks/SM.
// ---------------------------------------------------------------------------
#define SS_LD 516
#define QK_LD 68
#define ATTN_SMEM_BYTES ((32 * SS_LD + 2 * 64 * QK_LD) * 4)

__global__ __launch_bounds__(512, 2) void attn_mma_kernel(
    const float* __restrict__ Km, const float* __restrict__ V,
    float* __restrict__ QC)   // Q in, context out (in-place)
{
    extern __shared__ float sm[];
    float* Ssm = sm;                        // [32][516]
    float* KV0 = sm + 32 * SS_LD;           // [64][68] stage 0
    float* KV1 = KV0 + 64 * QK_LD;          // [64][68] stage 1 (Q overlay)

    int tid = threadIdx.x;
    int lane = tid & 31;
    int w = tid >> 5;
    int gid = lane >> 2, tig = lane & 3;
    int nt = w & 7;
    int mg = w >> 3;                        // 0..1
    int mrow = mg << 4;

    int hid = blockIdx.y;                   // (b, win, h)
    int b = hid >> 7;
    int wn = (hid >> 4) & 7;
    int h = hid & 15;
    int t0 = b * 4096 + wn * 512;
    int hcol = h << 6;
    int qbase = blockIdx.x << 5;            // 32 q-rows per block

    int r = tid >> 3;                       // 0..63 KV staging row
    int c0 = (tid & 7) << 3;                // 0..56 staging col (8 floats)

    // ---- stage Q (32x64) into KV1 + prefetch K tile 0 into KV0 ----
    {
        int qr = tid >> 4;                  // 0..31
        int qc = (tid & 15) << 2;           // 0..60
        float4 qv = *(const float4*)(QC + (size_t)(t0 + qbase + qr) * DDIM + hcol + qc);
        const float* ksrc = Km + (size_t)(t0 + r) * DDIM + hcol + c0;
        cp_async16(&KV0[r * QK_LD + c0], ksrc);
        cp_async16(&KV0[r * QK_LD + c0 + 4], ksrc + 4);
        cp_commit();
        *(float4*)&KV1[qr * QK_LD + qc] = qv;
    }
    __syncthreads();                        // Q visible

    // ---- hoist Q A-fragments from KV1 (k-invariant across key tiles) ----
    uint32_t af[8][4];
#pragma unroll
    for (int ks = 0; ks < 8; ks++) {
        int kk = ks << 3;
        af[ks][0] = __float_as_uint(KV1[(mrow + gid) * QK_LD + kk + tig]);
        af[ks][1] = __float_as_uint(KV1[(mrow + gid + 8) * QK_LD + kk + tig]);
        af[ks][2] = __float_as_uint(KV1[(mrow + gid) * QK_LD + kk + tig + 4]);
        af[ks][3] = __float_as_uint(KV1[(mrow + gid + 8) * QK_LD + kk + tig + 4]);
    }
    cp_wait_all();
    __syncthreads();                        // af done (KV1 free), K0 visible

    // ---- scores S[32][512] = Q K^T via mma, pipelined over 8 key tiles ----
    for (int kt = 0; kt < 8; kt++) {
        float* cur = (kt & 1) ? KV1 : KV0;
        if (kt < 7) {
            float* nxt = (kt & 1) ? KV0 : KV1;
            const float* src = Km + (size_t)(t0 + (kt + 1) * 64 + r) * DDIM + hcol + c0;
            cp_async16(&nxt[r * QK_LD + c0], src);
            cp_async16(&nxt[r * QK_LD + c0 + 4], src + 4);
            cp_commit();
        }
        float s0 = 0.f, s1 = 0.f, s2 = 0.f, s3 = 0.f;
#pragma unroll
        for (int ks = 0; ks < 8; ks++) {
            int kk = ks << 3;
            uint32_t b0 = __float_as_uint(cur[((nt << 3) + gid) * QK_LD + kk + tig]);
            uint32_t b1 = __float_as_uint(cur[((nt << 3) + gid) * QK_LD + kk + tig + 4]);
            mma_tf32(s0, s1, s2, s3,
                     af[ks][0], af[ks][1], af[ks][2], af[ks][3], b0, b1);
        }
        {
            int row = mrow + gid;
            int col = kt * 64 + (nt << 3) + (tig << 1);
            *(float2*)&Ssm[row * SS_LD + col] = make_float2(s0, s1);
            *(float2*)&Ssm[(row + 8) * SS_LD + col] = make_float2(s2, s3);
        }
        cp_wait_all();
        __syncthreads();
    }

    // prefetch V tile 0 into KV0 (both buffers free), overlaps softmax
    {
        const float* src = V + (size_t)(t0 + r) * DDIM + hcol + c0;
        cp_async16(&KV0[r * QK_LD + c0], src);
        cp_async16(&KV0[r * QK_LD + c0 + 4], src + 4);
        cp_commit();
    }

    // ---- softmax over 512 keys per row (2 rows per warp), scale 0.125 ----
    {
#pragma unroll
        for (int q = 0; q < 2; q++) {
            int rr = (w << 1) + q;
            float vals[16];
            float m = -1e30f;
#pragma unroll
            for (int t = 0; t < 16; t++) {
                vals[t] = Ssm[rr * SS_LD + lane + 32 * t];
                m = fmaxf(m, vals[t]);
            }
#pragma unroll
            for (int off = 16; off > 0; off >>= 1)
                m = fmaxf(m, __shfl_xor_sync(0xffffffffu, m, off));
            float s = 0.f;
#pragma unroll
            for (int t = 0; t < 16; t++) {
                float e = __expf((vals[t] - m) * 0.125f);
                vals[t] = e;
                s += e;
            }
#pragma unroll
            for (int off = 16; off > 0; off >>= 1)
                s += __shfl_xor_sync(0xffffffffu, s, off);
            float inv = 1.0f / s;
#pragma unroll
            for (int t = 0; t < 16; t++)
                Ssm[rr * SS_LD + lane + 32 * t] = vals[t] * inv;
        }
    }
    cp_wait_all();
    __syncthreads();   // V0 ready; softmax writes visible

    // ---- O[32][64] = P[32][512] @ V[512][64], pipelined ----
    float o0 = 0.f, o1 = 0.f, o2 = 0.f, o3 = 0.f;

    for (int kt = 0; kt < 8; kt++) {
        float* cur = (kt & 1) ? KV1 : KV0;
        if (kt < 7) {
            float* nxt = (kt & 1) ? KV0 : KV1;
            const float* src = V + (size_t)(t0 + (kt + 1) * 64 + r) * DDIM + hcol + c0;
            cp_async16(&nxt[r * QK_LD + c0], src);
            cp_async16(&nxt[r * QK_LD + c0 + 4], src + 4);
            cp_commit();
        }
#pragma unroll
        for (int ks = 0; ks < 8; ks++) {
            int kk = ks << 3;
            uint32_t b0 = __float_as_uint(cur[(kk + tig) * QK_LD + (nt << 3) + gid]);
            uint32_t b1 = __float_as_uint(cur[(kk + tig + 4) * QK_LD + (nt << 3) + gid]);
            int kc = kt * 64 + kk;
            uint32_t a0 = __float_as_uint(Ssm[(mrow + gid) * SS_LD + kc + tig]);
            uint32_t a1 = __float_as_uint(Ssm[(mrow + gid + 8) * SS_LD + kc + tig]);
            uint32_t a2 = __float_as_uint(Ssm[(mrow + gid) * SS_LD + kc + tig + 4]);
            uint32_t a3 = __float_as_uint(Ssm[(mrow + gid + 8) * SS_LD + kc + tig + 4]);
            mma_tf32(o0, o1, o2, o3, a0, a1, a2, a3, b0, b1);
        }
        cp_wait_all();
        __syncthreads();
    }

    // ---- store context in-place over Q ----
    {
        size_t row = (size_t)t0 + qbase + mrow + gid;
        int col = hcol + (nt << 3) + (tig << 1);
        *(float2*)(QC + row * DDIM + col) = make_float2(o0, o1);
        *(float2*)(QC + (row + 8) * DDIM + col) = make_float2(o2, o3);
    }
}

// ---------------------------------------------------------------------------
// LayerNorm per row (1024 elems), keras eps = 1e-3. One block per row.
// ---------------------------------------------------------------------------
__global__ __launch_bounds__(256) void ln_kernel(
    const float* __restrict__ Y, const float* __restrict__ gamma,
    const float* __restrict__ beta, float* __restrict__ out)
{
    int row = blockIdx.x;
    int tid = threadIdx.x;
    const float* y = Y + (size_t)row * DDIM;

    float4 v = *(const float4*)(y + tid * 4);
    float s  = v.x + v.y + v.z + v.w;
    float sq = v.x * v.x + v.y * v.y + v.z * v.z + v.w * v.w;

#pragma unroll
    for (int off = 16; off > 0; off >>= 1) {
        s  += __shfl_xor_sync(0xffffffffu, s, off);
        sq += __shfl_xor_sync(0xffffffffu, sq, off);
    }
    __shared__ float ss[8], ssq[8];
    int lane = tid & 31, wid = tid >> 5;
    if (lane == 0) { ss[wid] = s; ssq[wid] = sq; }
    __syncthreads();
    float S = 0.f, SQ = 0.f;
#pragma unroll
    for (int i = 0; i < 8; i++) { S += ss[i]; SQ += ssq[i]; }

    float mu  = S * (1.0f / 1024.0f);
    float var = SQ * (1.0f / 1024.0f) - mu * mu;
    float inv = rsqrtf(var + 1e-3f);

    float4 g  = *(const float4*)(gamma + tid * 4);
    float4 be = *(const float4*)(beta + tid * 4);
    float4 o;
    o.x = (v.x - mu) * inv * g.x + be.x;
    o.y = (v.y - mu) * inv * g.y + be.y;
    o.z = (v.z - mu) * inv * g.z + be.z;
    o.w = (v.w - mu) * inv * g.w + be.w;
    *(float4*)(out + (size_t)row * DDIM + tid * 4) = o;
}

// ---------------------------------------------------------------------------
extern "C" void kernel_launch(void* const* d_in, const int* in_sizes, int n_in,
                              void* d_out, int out_size)
{
    const float* x     = (const float*)d_in[0];
    const float* Wq    = (const float*)d_in[1];
    const float* bq    = (const float*)d_in[2];
    const float* Wk    = (const float*)d_in[3];
    const float* bk    = (const float*)d_in[4];
    const float* Wv    = (const float*)d_in[5];
    const float* bv    = (const float*)d_in[6];
    const float* Wo    = (const float*)d_in[7];
    const float* bo    = (const float*)d_in[8];
    const float* gamma = (const float*)d_in[9];
    const float* beta  = (const float*)d_in[10];
    float* out = (float*)d_out;
    (void)in_sizes; (void)n_in; (void)out_size;

    float *Qp, *Kp, *Vp;
    cudaGetSymbolAddress((void**)&Qp, g_Q);
    cudaGetSymbolAddress((void**)&Kp, g_K);
    cudaGetSymbolAddress((void**)&Vp, g_V);

    cudaFuncSetAttribute(tf32_gemm3_kernel,
                         cudaFuncAttributeMaxDynamicSharedMemorySize, GEMM_SMEM_BYTES);
    cudaFuncSetAttribute(attn_mma_kernel,
                         cudaFuncAttributeMaxDynamicSharedMemorySize, ATTN_SMEM_BYTES);

    // Q, K, V in one launch: z selects weights/bias/output
    tf32_gemm3_kernel<<<dim3(8, 128, 3), 256, GEMM_SMEM_BYTES>>>(
        x, Wq, Wk, Wv, bq, bk, bv, nullptr, Qp, Kp, Vp);

    // ctx overwrites Q in-place; grid: 16 q-tiles of 32 x 512 heads
    attn_mma_kernel<<<dim3(16, 512), 512, ATTN_SMEM_BYTES>>>(Kp, Vp, Qp);

    // Y = ctx @ Wo + bo + x   (write Y into g_K, dead after attention)
    tf32_gemm3_kernel<<<dim3(8, 128, 1), 256, GEMM_SMEM_BYTES>>>(
        Qp, Wo, Wo, Wo, bo, bo, bo, x, Kp, Kp, Kp);

    ln_kernel<<<M_TOK, 256>>>(Kp, gamma, beta, out);
}